// round 14
// baseline (speedup 1.0000x reference)
#include <cuda_runtime.h>
#include <cuda_fp16.h>
#include <cstdint>

// Problem constants
#define BB 4
#define TT 2048
#define CC 1024
#define HH 16
#define HD 64
#define MTOK (BB*TT)        // 8192
#define C3  (3*CC)          // 3072

// 0.125 (1/sqrt(64)) * log2(e): folded into Q so attention can use exp2
#define QSCALE 0.18033688f

// Scratch (allocation-guard-safe: __device__ globals). fp16 pairs stored as u32.
__device__ uint32_t g_xf[(size_t)MTOK * CC / 2];
__device__ uint32_t g_w1f[(size_t)C3 * CC / 2];
__device__ uint32_t g_w2f[(size_t)CC * CC / 2];
__device__ uint32_t g_qkvf[(size_t)MTOK * C3 / 2];
__device__ uint32_t g_atf[(size_t)MTOK * CC / 2];
__device__ int g_ctr[4];   // dynamic tile counters (reset each launch)

// ---------------------------------------------------------------------------
// Helpers
// ---------------------------------------------------------------------------
__device__ __forceinline__ uint32_t smem_u32(const void* p) {
    uint32_t a;
    asm("{ .reg .u64 t; cvta.to.shared.u64 t, %1; cvt.u32.u64 %0, t; }" : "=r"(a) : "l"(p));
    return a;
}
__device__ __forceinline__ uint32_t f16x2_of(float lo, float hi) {
    uint32_t r;
    asm("cvt.rn.f16x2.f32 %0, %1, %2;" : "=r"(r) : "f"(hi), "f"(lo));
    return r;
}
__device__ __forceinline__ void cp16(uint32_t s, const void* g) {
    asm volatile("cp.async.cg.shared.global [%0], [%1], 16;" :: "r"(s), "l"(g) : "memory");
}
__device__ __forceinline__ void cpcommit() {
    asm volatile("cp.async.commit_group;" ::: "memory");
}
__device__ __forceinline__ void cpwait0() { asm volatile("cp.async.wait_group 0;" ::: "memory"); }
__device__ __forceinline__ void cpwait1() { asm volatile("cp.async.wait_group 1;" ::: "memory"); }
__device__ __forceinline__ void ldsm4(uint32_t* r, uint32_t a) {
    asm volatile("ldmatrix.sync.aligned.m8n8.x4.shared.b16 {%0,%1,%2,%3}, [%4];"
        : "=r"(r[0]), "=r"(r[1]), "=r"(r[2]), "=r"(r[3]) : "r"(a));
}
__device__ __forceinline__ void ldsm4t(uint32_t* r, uint32_t a) {
    asm volatile("ldmatrix.sync.aligned.m8n8.x4.trans.shared.b16 {%0,%1,%2,%3}, [%4];"
        : "=r"(r[0]), "=r"(r[1]), "=r"(r[2]), "=r"(r[3]) : "r"(a));
}
__device__ __forceinline__ void mma16816(float* c, const uint32_t* a, const uint32_t* b) {
    asm volatile("mma.sync.aligned.m16n8k16.row.col.f32.f16.f16.f32 "
        "{%0,%1,%2,%3}, {%4,%5,%6,%7}, {%8,%9}, {%0,%1,%2,%3};"
        : "+f"(c[0]), "+f"(c[1]), "+f"(c[2]), "+f"(c[3])
        : "r"(a[0]), "r"(a[1]), "r"(a[2]), "r"(a[3]), "r"(b[0]), "r"(b[1]));
}
// 128B-row swizzle: 8 chunks of 16B, chunk ^ (row & 7)
__device__ __forceinline__ uint32_t swz(uint32_t base, int row, int chunk) {
    return base + (uint32_t)(row * 128) + (uint32_t)((chunk ^ (row & 7)) << 4);
}

// ---------------------------------------------------------------------------
// Fused conversion: fp32 -> fp16 for x, w1, w2 in one launch
// ---------------------------------------------------------------------------
__global__ void cvt_all(const float4* __restrict__ s0, uint32_t* __restrict__ d0, int n0,
                        const float4* __restrict__ s1, uint32_t* __restrict__ d1, int n1,
                        const float4* __restrict__ s2, uint32_t* __restrict__ d2, int n2)
{
    int i = blockIdx.x * blockDim.x + threadIdx.x;
    const float4* s; uint32_t* d; int j;
    if (i < n0)            { s = s0; d = d0; j = i; }
    else if (i < n0 + n1)  { s = s1; d = d1; j = i - n0; }
    else if (i < n0+n1+n2) { s = s2; d = d2; j = i - n0 - n1; }
    else return;
    float4 f = s[j];
    *(uint2*)&d[2 * j] = make_uint2(f16x2_of(f.x, f.y), f16x2_of(f.z, f.w));
}

// ---------------------------------------------------------------------------
// Persistent GEMM via mma.sync (single-pass fp16), BK=64, warp tile 64x32.
// Grid 296 CTAs; tiles claimed dynamically via g_ctr[ctr_idx].
// qcols/qmul: columns < qcols get (acc+bias)*qmul (Q pre-scaling for attn).
// ---------------------------------------------------------------------------
#define BK 64
#define STAGES 3
#define SBYTES 32768
#define GEMM_DSM (STAGES * SBYTES + 1024)

template<bool OUT_HALF>
__global__ void __launch_bounds__(256, 2)
gemm_mma(const uint32_t* __restrict__ A2, const uint32_t* __restrict__ B2,
         const float* __restrict__ bias,
         float* __restrict__ OutF, uint32_t* __restrict__ OutH,
         int M, int N, int K, int ntN, int ntiles, int ctr_idx,
         int qcols, float qmul)
{
    extern __shared__ char dsm[];
    __shared__ int s_tile;
    const uint32_t sbase = (smem_u32(dsm) + 1023u) & ~1023u;

    const int tid  = threadIdx.x;
    const int lane = tid & 31;
    const int warp = tid >> 5;
    const int wm = warp & 1;
    const int wn = warp >> 1;
    const int lr = tid >> 3;
    const int lc = tid & 7;
    const int NKI = K / BK;

    for (;;) {
        if (tid == 0) s_tile = atomicAdd(&g_ctr[ctr_idx], 1);
        __syncthreads();
        const int t = s_tile;
        if (t >= ntiles) break;
        const int m0 = (t / ntN) * 128;
        const int n0 = (t % ntN) * 128;

        const char* pA = (const char*)A2 + (size_t)m0 * K * 2;
        const char* pB = (const char*)B2 + (size_t)n0 * K * 2;

        float acc[4][4][4] = {};

        auto load_stage = [&](int s, int it) {
            const uint32_t ss = sbase + s * SBYTES;
            const int gko = it * BK * 2;
            #pragma unroll
            for (int i = 0; i < 4; i++) {
                int r = lr + i * 32;
                cp16(swz(ss, r, lc), pA + (size_t)r * K * 2 + gko + lc * 16);
                cp16(swz(ss + 16384, r, lc), pB + (size_t)r * K * 2 + gko + lc * 16);
            }
        };
        auto compute_stage = [&](int s) {
            const uint32_t ss = sbase + s * SBYTES;
            #pragma unroll
            for (int ks = 0; ks < 4; ks++) {
                uint32_t a[4][4];
                #pragma unroll
                for (int mt = 0; mt < 4; mt++) {
                    int row = wm * 64 + mt * 16 + (lane & 15);
                    int kc  = ks * 2 + (lane >> 4);
                    ldsm4(a[mt], swz(ss, row, kc));
                }
                uint32_t b[2][4];
                #pragma unroll
                for (int jj = 0; jj < 2; jj++) {
                    int row = wn * 32 + jj * 16 + (lane & 7) + ((lane >> 4) << 3);
                    int kc  = ks * 2 + ((lane >> 3) & 1);
                    ldsm4(b[jj], swz(ss + 16384, row, kc));
                }
                #pragma unroll
                for (int mt = 0; mt < 4; mt++)
                    #pragma unroll
                    for (int nt = 0; nt < 4; nt++)
                        mma16816(acc[mt][nt], a[mt], &b[nt >> 1][(nt & 1) * 2]);
            }
        };

        #pragma unroll
        for (int s = 0; s < STAGES - 1; s++) { load_stage(s, s); cpcommit(); }

        for (int it = 0; it < NKI; it++) {
            asm volatile("cp.async.wait_group %0;" :: "n"(STAGES - 2) : "memory");
            __syncthreads();
            const int nit = it + STAGES - 1;
            if (nit < NKI) load_stage(nit % STAGES, nit);
            cpcommit();
            compute_stage(it % STAGES);
        }

        const int rr = lane >> 2;
        const int cc = (lane & 3) * 2;
        #pragma unroll
        for (int mt = 0; mt < 4; mt++)
            #pragma unroll
            for (int nt = 0; nt < 4; nt++) {
                const int col = n0 + wn * 32 + nt * 8 + cc;
                const float b0 = bias[col], b1 = bias[col + 1];
                const float mul = (col < qcols) ? qmul : 1.0f;
                #pragma unroll
                for (int hf = 0; hf < 2; hf++) {
                    const int row = m0 + wm * 64 + mt * 16 + rr + hf * 8;
                    float v0 = (acc[mt][nt][hf * 2 + 0] + b0) * mul;
                    float v1 = (acc[mt][nt][hf * 2 + 1] + b1) * mul;
                    if (OUT_HALF) {
                        OutH[((size_t)row * N + col) >> 1] = f16x2_of(v0, v1);
                    } else {
                        *(float2*)&OutF[(size_t)row * N + col] = make_float2(v0, v1);
                    }
                }
            }
    }
}

// ---------------------------------------------------------------------------
// Persistent flash attention (causal), fp16, QTILE=256, KTILE=128.
// Q pre-scaled by 0.125*log2e in gemm1 -> softmax uses exp2f, no scale muls.
// oacc rescale skipped warp-uniformly when no running max changed.
// ---------------------------------------------------------------------------
#define QTILE 256
#define KTILE 128
#define ASTAGE 32768
#define ATTN_DSM (32768 + 2 * ASTAGE + 1024)
#define NQT (TT / QTILE)          // 8
#define NITEMS (NQT * HH * BB)    // 512

__global__ void __launch_bounds__(256, 1)
attn_mma(const uint32_t* __restrict__ qkvf, uint32_t* __restrict__ of)
{
    extern __shared__ char dsm[];
    __shared__ int s_item;
    const uint32_t sb = (smem_u32(dsm) + 1023u) & ~1023u;
    const uint32_t sQ = sb, sStage = sb + 32768;

    const int tid = threadIdx.x;
    const int lane = tid & 31;
    const int wm = tid >> 5;
    const char* pf = (const char*)qkvf;

    for (;;) {
        if (tid == 0) s_item = atomicAdd(&g_ctr[2], 1);
        __syncthreads();
        const int w = s_item;
        if (w >= NITEMS) break;
        const int qt = NQT - 1 - (w / (HH * BB));       // heavy first
        const int hb = w % (HH * BB);
        const int h  = hb >> 2;
        const int b  = hb & 3;
        const int t0 = qt * QTILE;
        const int bT = b * TT;
        const int nkt = 2 * (qt + 1);

        auto load_q = [&]() {
            #pragma unroll
            for (int i = 0; i < 8; i++) {
                int idx = i * 256 + tid;
                int r = idx >> 3, c = idx & 7;
                cp16(swz(sQ, r, c), pf + ((size_t)(bT + t0 + r) * C3 + h * HD) * 2 + c * 16);
            }
        };
        auto load_kv = [&](int kt, int buf) {
            const uint32_t ss = sStage + buf * ASTAGE;
            const int c = tid & 7;
            #pragma unroll
            for (int i = 0; i < 4; i++) {
                int r = (tid >> 3) + i * 32;
                size_t rowg = (size_t)(bT + kt * KTILE + r) * C3;
                cp16(swz(ss,         r, c), pf + (rowg + CC + h * HD) * 2 + c * 16);
                cp16(swz(ss + 16384, r, c), pf + (rowg + 2 * CC + h * HD) * 2 + c * 16);
            }
        };

        load_q();
        load_kv(0, 0);
        cpcommit();

        uint32_t qf[2][4][4];
        float oacc[2][8][4] = {};
        float m_prev[2][2] = {{-1e30f, -1e30f}, {-1e30f, -1e30f}};
        float l_run[2][2] = {};
        bool qload = false;

        for (int kt = 0; kt < nkt; kt++) {
            if (kt + 1 < nkt) { load_kv(kt + 1, (kt + 1) & 1); cpcommit(); cpwait1(); }
            else cpwait0();
            __syncthreads();

            if (!qload) {
                qload = true;
                #pragma unroll
                for (int mt = 0; mt < 2; mt++)
                    #pragma unroll
                    for (int ks = 0; ks < 4; ks++) {
                        int row = wm * 32 + mt * 16 + (lane & 15);
                        int c = ks * 2 + (lane >> 4);
                        ldsm4(qf[mt][ks], swz(sQ, row, c));
                    }
            }

            const uint32_t ss = sStage + (kt & 1) * ASTAGE;

            #pragma unroll
            for (int sub = 0; sub < 2; sub++) {
                const int cb = kt * KTILE + sub * 64;
                const bool doCompute = cb <= (t0 + wm * 32 + 31);
                if (!doCompute) continue;

                float sacc[2][8][4] = {};
                #pragma unroll
                for (int ks = 0; ks < 4; ks++) {
                    uint32_t bh[4][4];
                    #pragma unroll
                    for (int jj = 0; jj < 4; jj++) {
                        int row = sub * 64 + jj * 16 + (lane & 7) + ((lane >> 4) << 3);
                        int c = ks * 2 + ((lane >> 3) & 1);
                        ldsm4(bh[jj], swz(ss, row, c));
                    }
                    #pragma unroll
                    for (int mt = 0; mt < 2; mt++)
                        #pragma unroll
                        for (int nt = 0; nt < 8; nt++)
                            mma16816(sacc[mt][nt], qf[mt][ks], &bh[nt >> 1][(nt & 1) * 2]);
                }

                #pragma unroll
                for (int mt = 0; mt < 2; mt++) {
                    const int rbase = t0 + wm * 32 + mt * 16;
                    // causal mask (diagonal subtiles only); logits already log2-scaled
                    if ((cb + 63) > rbase) {
                        #pragma unroll
                        for (int nt = 0; nt < 8; nt++)
                            #pragma unroll
                            for (int e = 0; e < 4; e++) {
                                int rg = rbase + (lane >> 2) + (e >> 1) * 8;
                                int cg = cb + nt * 8 + (lane & 3) * 2 + (e & 1);
                                if (cg > rg) sacc[mt][nt][e] = -1e30f;
                            }
                    }

                    #pragma unroll
                    for (int rh = 0; rh < 2; rh++) {
                        float mloc = -1e30f;
                        #pragma unroll
                        for (int nt = 0; nt < 8; nt++)
                            mloc = fmaxf(mloc, fmaxf(sacc[mt][nt][rh * 2], sacc[mt][nt][rh * 2 + 1]));
                        mloc = fmaxf(mloc, __shfl_xor_sync(0xffffffffu, mloc, 1));
                        mloc = fmaxf(mloc, __shfl_xor_sync(0xffffffffu, mloc, 2));
                        float mnew = fmaxf(m_prev[mt][rh], mloc);
                        const bool chg = mnew > m_prev[mt][rh];
                        if (__any_sync(0xffffffffu, chg)) {
                            float corr = exp2f(m_prev[mt][rh] - mnew);
                            m_prev[mt][rh] = mnew;
                            l_run[mt][rh] *= corr;
                            #pragma unroll
                            for (int nt = 0; nt < 8; nt++) {
                                oacc[mt][nt][rh * 2]     *= corr;
                                oacc[mt][nt][rh * 2 + 1] *= corr;
                            }
                        }
                        float ls = 0.0f;
                        #pragma unroll
                        for (int nt = 0; nt < 8; nt++) {
                            float p0 = exp2f(sacc[mt][nt][rh * 2]     - mnew);
                            float p1 = exp2f(sacc[mt][nt][rh * 2 + 1] - mnew);
                            sacc[mt][nt][rh * 2] = p0; sacc[mt][nt][rh * 2 + 1] = p1;
                            ls += p0 + p1;
                        }
                        ls += __shfl_xor_sync(0xffffffffu, ls, 1);
                        ls += __shfl_xor_sync(0xffffffffu, ls, 2);
                        l_run[mt][rh] += ls;
                    }
                }

                #pragma unroll
                for (int jp = 0; jp < 4; jp++) {
                    uint32_t vh[4][4];
                    #pragma unroll
                    for (int jd = 0; jd < 4; jd++) {
                        int row = sub * 64 + jp * 16 + (lane & 7) + (((lane >> 3) & 1) << 3);
                        int c = 2 * jd + (lane >> 4);
                        ldsm4t(vh[jd], swz(ss + 16384, row, c));
                    }
                    #pragma unroll
                    for (int mt = 0; mt < 2; mt++) {
                        uint32_t pa[4];
                        const float* f0 = sacc[mt][2 * jp];
                        const float* f1 = sacc[mt][2 * jp + 1];
                        pa[0] = f16x2_of(f0[0], f0[1]);
                        pa[1] = f16x2_of(f0[2], f0[3]);
                        pa[2] = f16x2_of(f1[0], f1[1]);
                        pa[3] = f16x2_of(f1[2], f1[3]);
                        #pragma unroll
                        for (int nt = 0; nt < 8; nt++)
                            mma16816(oacc[mt][nt], pa, &vh[nt >> 1][(nt & 1) * 2]);
                    }
                }
            }
            __syncthreads();
        }

        #pragma unroll
        for (int mt = 0; mt < 2; mt++)
            #pragma unroll
            for (int rh = 0; rh < 2; rh++) {
                float iv = 1.0f / l_run[mt][rh];
                #pragma unroll
                for (int nt = 0; nt < 8; nt++) {
                    float o0 = oacc[mt][nt][rh * 2] * iv;
                    float o1 = oacc[mt][nt][rh * 2 + 1] * iv;
                    size_t token = (size_t)(bT + t0 + wm * 32 + mt * 16 + (lane >> 2) + rh * 8);
                    of[(token * CC + h * HD + nt * 8 + (lane & 3) * 2) >> 1] = f16x2_of(o0, o1);
                }
            }
    }
}

// ---------------------------------------------------------------------------
// Launch
// ---------------------------------------------------------------------------
extern "C" void kernel_launch(void* const* d_in, const int* in_sizes, int n_in,
                              void* d_out, int out_size)
{
    const float* x      = (const float*)d_in[0];
    const float* qkv_w  = (const float*)d_in[1];
    const float* qkv_b  = (const float*)d_in[2];
    const float* out_w  = (const float*)d_in[3];
    const float* out_b  = (const float*)d_in[4];
    float* out = (float*)d_out;

    uint32_t *xf, *w1f, *w2f, *qf, *atf;
    int* ctr;
    cudaGetSymbolAddress((void**)&xf, g_xf);
    cudaGetSymbolAddress((void**)&w1f, g_w1f);
    cudaGetSymbolAddress((void**)&w2f, g_w2f);
    cudaGetSymbolAddress((void**)&qf, g_qkvf);
    cudaGetSymbolAddress((void**)&atf, g_atf);
    cudaGetSymbolAddress((void**)&ctr, g_ctr);

    cudaFuncSetAttribute(gemm_mma<true>,  cudaFuncAttributeMaxDynamicSharedMemorySize, GEMM_DSM);
    cudaFuncSetAttribute(gemm_mma<false>, cudaFuncAttributeMaxDynamicSharedMemorySize, GEMM_DSM);
    cudaFuncSetAttribute(attn_mma, cudaFuncAttributeMaxDynamicSharedMemorySize, ATTN_DSM);

    // reset dynamic-tile counters (async memset is graph-capturable)
    cudaMemsetAsync(ctr, 0, 4 * sizeof(int));

    // 0) fused fp32->fp16 converts
    {
        const int n0 = MTOK * CC / 4, n1 = C3 * CC / 4, n2 = CC * CC / 4;
        const int nt = n0 + n1 + n2;
        cvt_all<<<(nt + 255) / 256, 256>>>((const float4*)x, xf, n0,
                                           (const float4*)qkv_w, w1f, n1,
                                           (const float4*)out_w, w2f, n2);
    }
    // 1) QKV projection -> fp16 qkv; Q columns pre-scaled by 0.125*log2(e)
    gemm_mma<true><<<296, 256, GEMM_DSM>>>(xf, w1f, qkv_b, nullptr, qf,
                                           MTOK, C3, CC, C3 / 128,
                                           (MTOK / 128) * (C3 / 128), 1,
                                           CC, QSCALE);
    // 2) Causal flash attention -> fp16 (persistent, dynamic items)
    attn_mma<<<148, 256, ATTN_DSM>>>(qf, atf);
    // 3) Output projection -> fp32
    gemm_mma<false><<<296, 256, GEMM_DSM>>>(atf, w2f, out_b, out, nullptr,
                                            MTOK, CC, CC, CC / 128,
                                            (MTOK / 128) * (CC / 128), 3,
                                            0, 1.0f);
}

// round 15
// speedup vs baseline: 1.0447x; 1.0447x over previous
#include <cuda_runtime.h>
#include <cuda_fp16.h>
#include <cstdint>

// Problem constants
#define BB 4
#define TT 2048
#define CC 1024
#define HH 16
#define HD 64
#define MTOK (BB*TT)        // 8192
#define C3  (3*CC)          // 3072

// 0.125 (1/sqrt(64)) * log2(e): folded into Q so attention can use exp2
#define QSCALE 0.18033688f

// Scratch (allocation-guard-safe: __device__ globals). fp16 pairs stored as u32.
__device__ uint32_t g_xf[(size_t)MTOK * CC / 2];
__device__ uint32_t g_w1f[(size_t)C3 * CC / 2];
__device__ uint32_t g_w2f[(size_t)CC * CC / 2];
__device__ uint32_t g_qkvf[(size_t)MTOK * C3 / 2];
__device__ uint32_t g_atf[(size_t)MTOK * CC / 2];
__device__ int g_ctr[4];   // dynamic tile counters (reset each launch)

// ---------------------------------------------------------------------------
// Helpers
// ---------------------------------------------------------------------------
__device__ __forceinline__ uint32_t smem_u32(const void* p) {
    uint32_t a;
    asm("{ .reg .u64 t; cvta.to.shared.u64 t, %1; cvt.u32.u64 %0, t; }" : "=r"(a) : "l"(p));
    return a;
}
__device__ __forceinline__ uint32_t f16x2_of(float lo, float hi) {
    uint32_t r;
    asm("cvt.rn.f16x2.f32 %0, %1, %2;" : "=r"(r) : "f"(hi), "f"(lo));
    return r;
}
__device__ __forceinline__ void cp16(uint32_t s, const void* g) {
    asm volatile("cp.async.cg.shared.global [%0], [%1], 16;" :: "r"(s), "l"(g) : "memory");
}
__device__ __forceinline__ void cpcommit() {
    asm volatile("cp.async.commit_group;" ::: "memory");
}
__device__ __forceinline__ void cpwait0() { asm volatile("cp.async.wait_group 0;" ::: "memory"); }
__device__ __forceinline__ void cpwait1() { asm volatile("cp.async.wait_group 1;" ::: "memory"); }
__device__ __forceinline__ void ldsm4(uint32_t* r, uint32_t a) {
    asm volatile("ldmatrix.sync.aligned.m8n8.x4.shared.b16 {%0,%1,%2,%3}, [%4];"
        : "=r"(r[0]), "=r"(r[1]), "=r"(r[2]), "=r"(r[3]) : "r"(a));
}
__device__ __forceinline__ void ldsm4t(uint32_t* r, uint32_t a) {
    asm volatile("ldmatrix.sync.aligned.m8n8.x4.trans.shared.b16 {%0,%1,%2,%3}, [%4];"
        : "=r"(r[0]), "=r"(r[1]), "=r"(r[2]), "=r"(r[3]) : "r"(a));
}
__device__ __forceinline__ void mma16816(float* c, const uint32_t* a, const uint32_t* b) {
    asm volatile("mma.sync.aligned.m16n8k16.row.col.f32.f16.f16.f32 "
        "{%0,%1,%2,%3}, {%4,%5,%6,%7}, {%8,%9}, {%0,%1,%2,%3};"
        : "+f"(c[0]), "+f"(c[1]), "+f"(c[2]), "+f"(c[3])
        : "r"(a[0]), "r"(a[1]), "r"(a[2]), "r"(a[3]), "r"(b[0]), "r"(b[1]));
}
// 128B-row swizzle: 8 chunks of 16B, chunk ^ (row & 7)
__device__ __forceinline__ uint32_t swz(uint32_t base, int row, int chunk) {
    return base + (uint32_t)(row * 128) + (uint32_t)((chunk ^ (row & 7)) << 4);
}

// ---------------------------------------------------------------------------
// Fused conversion: fp32 -> fp16 for x, w1, w2 in one launch
// ---------------------------------------------------------------------------
__global__ void cvt_all(const float4* __restrict__ s0, uint32_t* __restrict__ d0, int n0,
                        const float4* __restrict__ s1, uint32_t* __restrict__ d1, int n1,
                        const float4* __restrict__ s2, uint32_t* __restrict__ d2, int n2)
{
    int i = blockIdx.x * blockDim.x + threadIdx.x;
    const float4* s; uint32_t* d; int j;
    if (i < n0)            { s = s0; d = d0; j = i; }
    else if (i < n0 + n1)  { s = s1; d = d1; j = i - n0; }
    else if (i < n0+n1+n2) { s = s2; d = d2; j = i - n0 - n1; }
    else return;
    float4 f = s[j];
    *(uint2*)&d[2 * j] = make_uint2(f16x2_of(f.x, f.y), f16x2_of(f.z, f.w));
}

// ---------------------------------------------------------------------------
// Persistent GEMM via mma.sync (single-pass fp16), BK=64, warp tile 64x32.
// Grid 296 CTAs; tiles claimed dynamically via g_ctr[ctr_idx].
// qcols/qmul: columns < qcols get (acc+bias)*qmul (Q pre-scaling for attn).
// ---------------------------------------------------------------------------
#define BK 64
#define STAGES 3
#define SBYTES 32768
#define GEMM_DSM (STAGES * SBYTES + 1024)

template<bool OUT_HALF>
__global__ void __launch_bounds__(256, 2)
gemm_mma(const uint32_t* __restrict__ A2, const uint32_t* __restrict__ B2,
         const float* __restrict__ bias,
         float* __restrict__ OutF, uint32_t* __restrict__ OutH,
         int M, int N, int K, int ntN, int ntiles, int ctr_idx,
         int qcols, float qmul)
{
    extern __shared__ char dsm[];
    __shared__ int s_tile;
    const uint32_t sbase = (smem_u32(dsm) + 1023u) & ~1023u;

    const int tid  = threadIdx.x;
    const int lane = tid & 31;
    const int warp = tid >> 5;
    const int wm = warp & 1;
    const int wn = warp >> 1;
    const int lr = tid >> 3;
    const int lc = tid & 7;
    const int NKI = K / BK;

    for (;;) {
        if (tid == 0) s_tile = atomicAdd(&g_ctr[ctr_idx], 1);
        __syncthreads();
        const int t = s_tile;
        if (t >= ntiles) break;
        const int m0 = (t / ntN) * 128;
        const int n0 = (t % ntN) * 128;

        const char* pA = (const char*)A2 + (size_t)m0 * K * 2;
        const char* pB = (const char*)B2 + (size_t)n0 * K * 2;

        float acc[4][4][4] = {};

        auto load_stage = [&](int s, int it) {
            const uint32_t ss = sbase + s * SBYTES;
            const int gko = it * BK * 2;
            #pragma unroll
            for (int i = 0; i < 4; i++) {
                int r = lr + i * 32;
                cp16(swz(ss, r, lc), pA + (size_t)r * K * 2 + gko + lc * 16);
                cp16(swz(ss + 16384, r, lc), pB + (size_t)r * K * 2 + gko + lc * 16);
            }
        };
        auto compute_stage = [&](int s) {
            const uint32_t ss = sbase + s * SBYTES;
            #pragma unroll
            for (int ks = 0; ks < 4; ks++) {
                uint32_t a[4][4];
                #pragma unroll
                for (int mt = 0; mt < 4; mt++) {
                    int row = wm * 64 + mt * 16 + (lane & 15);
                    int kc  = ks * 2 + (lane >> 4);
                    ldsm4(a[mt], swz(ss, row, kc));
                }
                uint32_t b[2][4];
                #pragma unroll
                for (int jj = 0; jj < 2; jj++) {
                    int row = wn * 32 + jj * 16 + (lane & 7) + ((lane >> 4) << 3);
                    int kc  = ks * 2 + ((lane >> 3) & 1);
                    ldsm4(b[jj], swz(ss + 16384, row, kc));
                }
                #pragma unroll
                for (int mt = 0; mt < 4; mt++)
                    #pragma unroll
                    for (int nt = 0; nt < 4; nt++)
                        mma16816(acc[mt][nt], a[mt], &b[nt >> 1][(nt & 1) * 2]);
            }
        };

        #pragma unroll
        for (int s = 0; s < STAGES - 1; s++) { load_stage(s, s); cpcommit(); }

        for (int it = 0; it < NKI; it++) {
            asm volatile("cp.async.wait_group %0;" :: "n"(STAGES - 2) : "memory");
            __syncthreads();
            const int nit = it + STAGES - 1;
            if (nit < NKI) load_stage(nit % STAGES, nit);
            cpcommit();
            compute_stage(it % STAGES);
        }

        const int rr = lane >> 2;
        const int cc = (lane & 3) * 2;
        #pragma unroll
        for (int mt = 0; mt < 4; mt++)
            #pragma unroll
            for (int nt = 0; nt < 4; nt++) {
                const int col = n0 + wn * 32 + nt * 8 + cc;
                const float b0 = bias[col], b1 = bias[col + 1];
                const float mul = (col < qcols) ? qmul : 1.0f;
                #pragma unroll
                for (int hf = 0; hf < 2; hf++) {
                    const int row = m0 + wm * 64 + mt * 16 + rr + hf * 8;
                    float v0 = (acc[mt][nt][hf * 2 + 0] + b0) * mul;
                    float v1 = (acc[mt][nt][hf * 2 + 1] + b1) * mul;
                    if (OUT_HALF) {
                        OutH[((size_t)row * N + col) >> 1] = f16x2_of(v0, v1);
                    } else {
                        *(float2*)&OutF[(size_t)row * N + col] = make_float2(v0, v1);
                    }
                }
            }
    }
}

// ---------------------------------------------------------------------------
// Persistent flash attention (causal), fp16, QTILE=256, KTILE=128.
// Q pre-scaled by 0.125*log2e in gemm1 -> softmax uses exp2f (no scale muls).
// Rescale path UNCONDITIONAL (R13 structure — the R14 guard regressed).
// ---------------------------------------------------------------------------
#define QTILE 256
#define KTILE 128
#define ASTAGE 32768
#define ATTN_DSM (32768 + 2 * ASTAGE + 1024)
#define NQT (TT / QTILE)          // 8
#define NITEMS (NQT * HH * BB)    // 512

__global__ void __launch_bounds__(256, 1)
attn_mma(const uint32_t* __restrict__ qkvf, uint32_t* __restrict__ of)
{
    extern __shared__ char dsm[];
    __shared__ int s_item;
    const uint32_t sb = (smem_u32(dsm) + 1023u) & ~1023u;
    const uint32_t sQ = sb, sStage = sb + 32768;

    const int tid = threadIdx.x;
    const int lane = tid & 31;
    const int wm = tid >> 5;
    const char* pf = (const char*)qkvf;

    for (;;) {
        if (tid == 0) s_item = atomicAdd(&g_ctr[2], 1);
        __syncthreads();
        const int w = s_item;
        if (w >= NITEMS) break;
        const int qt = NQT - 1 - (w / (HH * BB));       // heavy first
        const int hb = w % (HH * BB);
        const int h  = hb >> 2;
        const int b  = hb & 3;
        const int t0 = qt * QTILE;
        const int bT = b * TT;
        const int nkt = 2 * (qt + 1);

        auto load_q = [&]() {
            #pragma unroll
            for (int i = 0; i < 8; i++) {
                int idx = i * 256 + tid;
                int r = idx >> 3, c = idx & 7;
                cp16(swz(sQ, r, c), pf + ((size_t)(bT + t0 + r) * C3 + h * HD) * 2 + c * 16);
            }
        };
        auto load_kv = [&](int kt, int buf) {
            const uint32_t ss = sStage + buf * ASTAGE;
            const int c = tid & 7;
            #pragma unroll
            for (int i = 0; i < 4; i++) {
                int r = (tid >> 3) + i * 32;
                size_t rowg = (size_t)(bT + kt * KTILE + r) * C3;
                cp16(swz(ss,         r, c), pf + (rowg + CC + h * HD) * 2 + c * 16);
                cp16(swz(ss + 16384, r, c), pf + (rowg + 2 * CC + h * HD) * 2 + c * 16);
            }
        };

        load_q();
        load_kv(0, 0);
        cpcommit();

        uint32_t qf[2][4][4];
        float oacc[2][8][4] = {};
        float m_prev[2][2] = {{-1e30f, -1e30f}, {-1e30f, -1e30f}};
        float l_run[2][2] = {};
        bool qload = false;

        for (int kt = 0; kt < nkt; kt++) {
            if (kt + 1 < nkt) { load_kv(kt + 1, (kt + 1) & 1); cpcommit(); cpwait1(); }
            else cpwait0();
            __syncthreads();

            if (!qload) {
                qload = true;
                #pragma unroll
                for (int mt = 0; mt < 2; mt++)
                    #pragma unroll
                    for (int ks = 0; ks < 4; ks++) {
                        int row = wm * 32 + mt * 16 + (lane & 15);
                        int c = ks * 2 + (lane >> 4);
                        ldsm4(qf[mt][ks], swz(sQ, row, c));
                    }
            }

            const uint32_t ss = sStage + (kt & 1) * ASTAGE;

            #pragma unroll
            for (int sub = 0; sub < 2; sub++) {
                const int cb = kt * KTILE + sub * 64;
                const bool doCompute = cb <= (t0 + wm * 32 + 31);
                if (!doCompute) continue;

                float sacc[2][8][4] = {};
                #pragma unroll
                for (int ks = 0; ks < 4; ks++) {
                    uint32_t bh[4][4];
                    #pragma unroll
                    for (int jj = 0; jj < 4; jj++) {
                        int row = sub * 64 + jj * 16 + (lane & 7) + ((lane >> 4) << 3);
                        int c = ks * 2 + ((lane >> 3) & 1);
                        ldsm4(bh[jj], swz(ss, row, c));
                    }
                    #pragma unroll
                    for (int mt = 0; mt < 2; mt++)
                        #pragma unroll
                        for (int nt = 0; nt < 8; nt++)
                            mma16816(sacc[mt][nt], qf[mt][ks], &bh[nt >> 1][(nt & 1) * 2]);
                }

                #pragma unroll
                for (int mt = 0; mt < 2; mt++) {
                    const int rbase = t0 + wm * 32 + mt * 16;
                    // causal mask (diagonal subtiles only); logits already log2-scaled
                    if ((cb + 63) > rbase) {
                        #pragma unroll
                        for (int nt = 0; nt < 8; nt++)
                            #pragma unroll
                            for (int e = 0; e < 4; e++) {
                                int rg = rbase + (lane >> 2) + (e >> 1) * 8;
                                int cg = cb + nt * 8 + (lane & 3) * 2 + (e & 1);
                                if (cg > rg) sacc[mt][nt][e] = -1e30f;
                            }
                    }

                    #pragma unroll
                    for (int rh = 0; rh < 2; rh++) {
                        float mloc = -1e30f;
                        #pragma unroll
                        for (int nt = 0; nt < 8; nt++)
                            mloc = fmaxf(mloc, fmaxf(sacc[mt][nt][rh * 2], sacc[mt][nt][rh * 2 + 1]));
                        mloc = fmaxf(mloc, __shfl_xor_sync(0xffffffffu, mloc, 1));
                        mloc = fmaxf(mloc, __shfl_xor_sync(0xffffffffu, mloc, 2));
                        float mnew = fmaxf(m_prev[mt][rh], mloc);
                        float corr = exp2f(m_prev[mt][rh] - mnew);
                        m_prev[mt][rh] = mnew;
                        float ls = 0.0f;
                        #pragma unroll
                        for (int nt = 0; nt < 8; nt++) {
                            float p0 = exp2f(sacc[mt][nt][rh * 2]     - mnew);
                            float p1 = exp2f(sacc[mt][nt][rh * 2 + 1] - mnew);
                            sacc[mt][nt][rh * 2] = p0; sacc[mt][nt][rh * 2 + 1] = p1;
                            ls += p0 + p1;
                        }
                        ls += __shfl_xor_sync(0xffffffffu, ls, 1);
                        ls += __shfl_xor_sync(0xffffffffu, ls, 2);
                        l_run[mt][rh] = l_run[mt][rh] * corr + ls;
                        #pragma unroll
                        for (int nt = 0; nt < 8; nt++) {
                            oacc[mt][nt][rh * 2]     *= corr;
                            oacc[mt][nt][rh * 2 + 1] *= corr;
                        }
                    }
                }

                #pragma unroll
                for (int jp = 0; jp < 4; jp++) {
                    uint32_t vh[4][4];
                    #pragma unroll
                    for (int jd = 0; jd < 4; jd++) {
                        int row = sub * 64 + jp * 16 + (lane & 7) + (((lane >> 3) & 1) << 3);
                        int c = 2 * jd + (lane >> 4);
                        ldsm4t(vh[jd], swz(ss + 16384, row, c));
                    }
                    #pragma unroll
                    for (int mt = 0; mt < 2; mt++) {
                        uint32_t pa[4];
                        const float* f0 = sacc[mt][2 * jp];
                        const float* f1 = sacc[mt][2 * jp + 1];
                        pa[0] = f16x2_of(f0[0], f0[1]);
                        pa[1] = f16x2_of(f0[2], f0[3]);
                        pa[2] = f16x2_of(f1[0], f1[1]);
                        pa[3] = f16x2_of(f1[2], f1[3]);
                        #pragma unroll
                        for (int nt = 0; nt < 8; nt++)
                            mma16816(oacc[mt][nt], pa, &vh[nt >> 1][(nt & 1) * 2]);
                    }
                }
            }
            __syncthreads();
        }

        #pragma unroll
        for (int mt = 0; mt < 2; mt++)
            #pragma unroll
            for (int rh = 0; rh < 2; rh++) {
                float iv = 1.0f / l_run[mt][rh];
                #pragma unroll
                for (int nt = 0; nt < 8; nt++) {
                    float o0 = oacc[mt][nt][rh * 2] * iv;
                    float o1 = oacc[mt][nt][rh * 2 + 1] * iv;
                    size_t token = (size_t)(bT + t0 + wm * 32 + mt * 16 + (lane >> 2) + rh * 8);
                    of[(token * CC + h * HD + nt * 8 + (lane & 3) * 2) >> 1] = f16x2_of(o0, o1);
                }
            }
    }
}

// ---------------------------------------------------------------------------
// Launch
// ---------------------------------------------------------------------------
extern "C" void kernel_launch(void* const* d_in, const int* in_sizes, int n_in,
                              void* d_out, int out_size)
{
    const float* x      = (const float*)d_in[0];
    const float* qkv_w  = (const float*)d_in[1];
    const float* qkv_b  = (const float*)d_in[2];
    const float* out_w  = (const float*)d_in[3];
    const float* out_b  = (const float*)d_in[4];
    float* out = (float*)d_out;

    uint32_t *xf, *w1f, *w2f, *qf, *atf;
    int* ctr;
    cudaGetSymbolAddress((void**)&xf, g_xf);
    cudaGetSymbolAddress((void**)&w1f, g_w1f);
    cudaGetSymbolAddress((void**)&w2f, g_w2f);
    cudaGetSymbolAddress((void**)&qf, g_qkvf);
    cudaGetSymbolAddress((void**)&atf, g_atf);
    cudaGetSymbolAddress((void**)&ctr, g_ctr);

    cudaFuncSetAttribute(gemm_mma<true>,  cudaFuncAttributeMaxDynamicSharedMemorySize, GEMM_DSM);
    cudaFuncSetAttribute(gemm_mma<false>, cudaFuncAttributeMaxDynamicSharedMemorySize, GEMM_DSM);
    cudaFuncSetAttribute(attn_mma, cudaFuncAttributeMaxDynamicSharedMemorySize, ATTN_DSM);

    // reset dynamic-tile counters (async memset is graph-capturable)
    cudaMemsetAsync(ctr, 0, 4 * sizeof(int));

    // 0) fused fp32->fp16 converts
    {
        const int n0 = MTOK * CC / 4, n1 = C3 * CC / 4, n2 = CC * CC / 4;
        const int nt = n0 + n1 + n2;
        cvt_all<<<(nt + 255) / 256, 256>>>((const float4*)x, xf, n0,
                                           (const float4*)qkv_w, w1f, n1,
                                           (const float4*)out_w, w2f, n2);
    }
    // 1) QKV projection -> fp16 qkv; Q columns pre-scaled by 0.125*log2(e)
    gemm_mma<true><<<296, 256, GEMM_DSM>>>(xf, w1f, qkv_b, nullptr, qf,
                                           MTOK, C3, CC, C3 / 128,
                                           (MTOK / 128) * (C3 / 128), 1,
                                           CC, QSCALE);
    // 2) Causal flash attention -> fp16 (persistent, dynamic items)
    attn_mma<<<148, 256, ATTN_DSM>>>(qf, atf);
    // 3) Output projection -> fp32
    gemm_mma<false><<<296, 256, GEMM_DSM>>>(atf, w2f, out_b, out, nullptr,
                                            MTOK, CC, CC, CC / 128,
                                            (MTOK / 128) * (CC / 128), 3,
                                            0, 1.0f);
}

// round 16
// speedup vs baseline: 1.0600x; 1.0146x over previous
#include <cuda_runtime.h>
#include <cuda_fp16.h>
#include <cstdint>

// Problem constants
#define BB 4
#define TT 2048
#define CC 1024
#define HH 16
#define HD 64
#define MTOK (BB*TT)        // 8192
#define C3  (3*CC)          // 3072

// 0.125 (1/sqrt(64)) * log2(e): folded into Q so attention can use exp2
#define QSCALE 0.18033688f

// Scratch (allocation-guard-safe: __device__ globals). fp16 pairs stored as u32.
__device__ uint32_t g_xf[(size_t)MTOK * CC / 2];
__device__ uint32_t g_w1f[(size_t)C3 * CC / 2];
__device__ uint32_t g_w2f[(size_t)CC * CC / 2];
__device__ uint32_t g_qkvf[(size_t)MTOK * C3 / 2];
__device__ uint32_t g_atf[(size_t)MTOK * CC / 2];
__device__ int g_ctr[4];   // dynamic tile counters (reset each launch)

// ---------------------------------------------------------------------------
// Helpers
// ---------------------------------------------------------------------------
__device__ __forceinline__ uint32_t smem_u32(const void* p) {
    uint32_t a;
    asm("{ .reg .u64 t; cvta.to.shared.u64 t, %1; cvt.u32.u64 %0, t; }" : "=r"(a) : "l"(p));
    return a;
}
__device__ __forceinline__ uint32_t f16x2_of(float lo, float hi) {
    uint32_t r;
    asm("cvt.rn.f16x2.f32 %0, %1, %2;" : "=r"(r) : "f"(hi), "f"(lo));
    return r;
}
__device__ __forceinline__ void cp16(uint32_t s, const void* g) {
    asm volatile("cp.async.cg.shared.global [%0], [%1], 16;" :: "r"(s), "l"(g) : "memory");
}
__device__ __forceinline__ void cpcommit() {
    asm volatile("cp.async.commit_group;" ::: "memory");
}
__device__ __forceinline__ void cpwait0() { asm volatile("cp.async.wait_group 0;" ::: "memory"); }
__device__ __forceinline__ void cpwait1() { asm volatile("cp.async.wait_group 1;" ::: "memory"); }
__device__ __forceinline__ void ldsm4(uint32_t* r, uint32_t a) {
    asm volatile("ldmatrix.sync.aligned.m8n8.x4.shared.b16 {%0,%1,%2,%3}, [%4];"
        : "=r"(r[0]), "=r"(r[1]), "=r"(r[2]), "=r"(r[3]) : "r"(a));
}
__device__ __forceinline__ void ldsm4t(uint32_t* r, uint32_t a) {
    asm volatile("ldmatrix.sync.aligned.m8n8.x4.trans.shared.b16 {%0,%1,%2,%3}, [%4];"
        : "=r"(r[0]), "=r"(r[1]), "=r"(r[2]), "=r"(r[3]) : "r"(a));
}
__device__ __forceinline__ void mma16816(float* c, const uint32_t* a, const uint32_t* b) {
    asm volatile("mma.sync.aligned.m16n8k16.row.col.f32.f16.f16.f32 "
        "{%0,%1,%2,%3}, {%4,%5,%6,%7}, {%8,%9}, {%0,%1,%2,%3};"
        : "+f"(c[0]), "+f"(c[1]), "+f"(c[2]), "+f"(c[3])
        : "r"(a[0]), "r"(a[1]), "r"(a[2]), "r"(a[3]), "r"(b[0]), "r"(b[1]));
}
// 128B-row swizzle: 8 chunks of 16B, chunk ^ (row & 7)
__device__ __forceinline__ uint32_t swz(uint32_t base, int row, int chunk) {
    return base + (uint32_t)(row * 128) + (uint32_t)((chunk ^ (row & 7)) << 4);
}

// ---------------------------------------------------------------------------
// Fused conversion: fp32 -> fp16 for x, w1, w2 in one launch
// ---------------------------------------------------------------------------
__global__ void cvt_all(const float4* __restrict__ s0, uint32_t* __restrict__ d0, int n0,
                        const float4* __restrict__ s1, uint32_t* __restrict__ d1, int n1,
                        const float4* __restrict__ s2, uint32_t* __restrict__ d2, int n2)
{
    int i = blockIdx.x * blockDim.x + threadIdx.x;
    const float4* s; uint32_t* d; int j;
    if (i < n0)            { s = s0; d = d0; j = i; }
    else if (i < n0 + n1)  { s = s1; d = d1; j = i - n0; }
    else if (i < n0+n1+n2) { s = s2; d = d2; j = i - n0 - n1; }
    else return;
    float4 f = s[j];
    *(uint2*)&d[2 * j] = make_uint2(f16x2_of(f.x, f.y), f16x2_of(f.z, f.w));
}

// ---------------------------------------------------------------------------
// Persistent GEMM via mma.sync (single-pass fp16), BK=64, warp tile 64x32.
// Grid 296 CTAs; tiles claimed dynamically via g_ctr[ctr_idx].
// qcols/qmul: columns < qcols get (acc+bias)*qmul (Q pre-scaling for attn).
// ---------------------------------------------------------------------------
#define BK 64
#define STAGES 3
#define SBYTES 32768
#define GEMM_DSM (STAGES * SBYTES + 1024)

template<bool OUT_HALF>
__global__ void __launch_bounds__(256, 2)
gemm_mma(const uint32_t* __restrict__ A2, const uint32_t* __restrict__ B2,
         const float* __restrict__ bias,
         float* __restrict__ OutF, uint32_t* __restrict__ OutH,
         int M, int N, int K, int ntN, int ntiles, int ctr_idx,
         int qcols, float qmul)
{
    extern __shared__ char dsm[];
    __shared__ int s_tile;
    const uint32_t sbase = (smem_u32(dsm) + 1023u) & ~1023u;

    const int tid  = threadIdx.x;
    const int lane = tid & 31;
    const int warp = tid >> 5;
    const int wm = warp & 1;
    const int wn = warp >> 1;
    const int lr = tid >> 3;
    const int lc = tid & 7;
    const int NKI = K / BK;

    for (;;) {
        if (tid == 0) s_tile = atomicAdd(&g_ctr[ctr_idx], 1);
        __syncthreads();
        const int t = s_tile;
        if (t >= ntiles) break;
        const int m0 = (t / ntN) * 128;
        const int n0 = (t % ntN) * 128;

        const char* pA = (const char*)A2 + (size_t)m0 * K * 2;
        const char* pB = (const char*)B2 + (size_t)n0 * K * 2;

        float acc[4][4][4] = {};

        auto load_stage = [&](int s, int it) {
            const uint32_t ss = sbase + s * SBYTES;
            const int gko = it * BK * 2;
            #pragma unroll
            for (int i = 0; i < 4; i++) {
                int r = lr + i * 32;
                cp16(swz(ss, r, lc), pA + (size_t)r * K * 2 + gko + lc * 16);
                cp16(swz(ss + 16384, r, lc), pB + (size_t)r * K * 2 + gko + lc * 16);
            }
        };
        auto compute_stage = [&](int s) {
            const uint32_t ss = sbase + s * SBYTES;
            #pragma unroll
            for (int ks = 0; ks < 4; ks++) {
                uint32_t a[4][4];
                #pragma unroll
                for (int mt = 0; mt < 4; mt++) {
                    int row = wm * 64 + mt * 16 + (lane & 15);
                    int kc  = ks * 2 + (lane >> 4);
                    ldsm4(a[mt], swz(ss, row, kc));
                }
                uint32_t b[2][4];
                #pragma unroll
                for (int jj = 0; jj < 2; jj++) {
                    int row = wn * 32 + jj * 16 + (lane & 7) + ((lane >> 4) << 3);
                    int kc  = ks * 2 + ((lane >> 3) & 1);
                    ldsm4(b[jj], swz(ss + 16384, row, kc));
                }
                #pragma unroll
                for (int mt = 0; mt < 4; mt++)
                    #pragma unroll
                    for (int nt = 0; nt < 4; nt++)
                        mma16816(acc[mt][nt], a[mt], &b[nt >> 1][(nt & 1) * 2]);
            }
        };

        #pragma unroll
        for (int s = 0; s < STAGES - 1; s++) { load_stage(s, s); cpcommit(); }

        for (int it = 0; it < NKI; it++) {
            asm volatile("cp.async.wait_group %0;" :: "n"(STAGES - 2) : "memory");
            __syncthreads();
            const int nit = it + STAGES - 1;
            if (nit < NKI) load_stage(nit % STAGES, nit);
            cpcommit();
            compute_stage(it % STAGES);
        }

        const int rr = lane >> 2;
        const int cc = (lane & 3) * 2;
        #pragma unroll
        for (int mt = 0; mt < 4; mt++)
            #pragma unroll
            for (int nt = 0; nt < 4; nt++) {
                const int col = n0 + wn * 32 + nt * 8 + cc;
                const float b0 = bias[col], b1 = bias[col + 1];
                const float mul = (col < qcols) ? qmul : 1.0f;
                #pragma unroll
                for (int hf = 0; hf < 2; hf++) {
                    const int row = m0 + wm * 64 + mt * 16 + rr + hf * 8;
                    float v0 = (acc[mt][nt][hf * 2 + 0] + b0) * mul;
                    float v1 = (acc[mt][nt][hf * 2 + 1] + b1) * mul;
                    if (OUT_HALF) {
                        OutH[((size_t)row * N + col) >> 1] = f16x2_of(v0, v1);
                    } else {
                        *(float2*)&OutF[(size_t)row * N + col] = make_float2(v0, v1);
                    }
                }
            }
    }
}

// ---------------------------------------------------------------------------
// Persistent flash attention (causal), fp16, QTILE=256, KTILE=128.
// Q pre-scaled by 0.125*log2e in gemm1. Softmax exp via ex2.approx.f16x2:
// p computed directly as packed fp16 MMA fragments (half the MUFU ops,
// no separate pack step); l summed from the same fp16 p values.
// ---------------------------------------------------------------------------
#define QTILE 256
#define KTILE 128
#define ASTAGE 32768
#define ATTN_DSM (32768 + 2 * ASTAGE + 1024)
#define NQT (TT / QTILE)          // 8
#define NITEMS (NQT * HH * BB)    // 512

__global__ void __launch_bounds__(256, 1)
attn_mma(const uint32_t* __restrict__ qkvf, uint32_t* __restrict__ of)
{
    extern __shared__ char dsm[];
    __shared__ int s_item;
    const uint32_t sb = (smem_u32(dsm) + 1023u) & ~1023u;
    const uint32_t sQ = sb, sStage = sb + 32768;

    const int tid = threadIdx.x;
    const int lane = tid & 31;
    const int wm = tid >> 5;
    const char* pf = (const char*)qkvf;

    for (;;) {
        if (tid == 0) s_item = atomicAdd(&g_ctr[2], 1);
        __syncthreads();
        const int w = s_item;
        if (w >= NITEMS) break;
        const int qt = NQT - 1 - (w / (HH * BB));       // heavy first
        const int hb = w % (HH * BB);
        const int h  = hb >> 2;
        const int b  = hb & 3;
        const int t0 = qt * QTILE;
        const int bT = b * TT;
        const int nkt = 2 * (qt + 1);

        auto load_q = [&]() {
            #pragma unroll
            for (int i = 0; i < 8; i++) {
                int idx = i * 256 + tid;
                int r = idx >> 3, c = idx & 7;
                cp16(swz(sQ, r, c), pf + ((size_t)(bT + t0 + r) * C3 + h * HD) * 2 + c * 16);
            }
        };
        auto load_kv = [&](int kt, int buf) {
            const uint32_t ss = sStage + buf * ASTAGE;
            const int c = tid & 7;
            #pragma unroll
            for (int i = 0; i < 4; i++) {
                int r = (tid >> 3) + i * 32;
                size_t rowg = (size_t)(bT + kt * KTILE + r) * C3;
                cp16(swz(ss,         r, c), pf + (rowg + CC + h * HD) * 2 + c * 16);
                cp16(swz(ss + 16384, r, c), pf + (rowg + 2 * CC + h * HD) * 2 + c * 16);
            }
        };

        load_q();
        load_kv(0, 0);
        cpcommit();

        uint32_t qf[2][4][4];
        float oacc[2][8][4] = {};
        float m_prev[2][2] = {{-1e30f, -1e30f}, {-1e30f, -1e30f}};
        float l_run[2][2] = {};
        bool qload = false;

        for (int kt = 0; kt < nkt; kt++) {
            if (kt + 1 < nkt) { load_kv(kt + 1, (kt + 1) & 1); cpcommit(); cpwait1(); }
            else cpwait0();
            __syncthreads();

            if (!qload) {
                qload = true;
                #pragma unroll
                for (int mt = 0; mt < 2; mt++)
                    #pragma unroll
                    for (int ks = 0; ks < 4; ks++) {
                        int row = wm * 32 + mt * 16 + (lane & 15);
                        int c = ks * 2 + (lane >> 4);
                        ldsm4(qf[mt][ks], swz(sQ, row, c));
                    }
            }

            const uint32_t ss = sStage + (kt & 1) * ASTAGE;

            #pragma unroll
            for (int sub = 0; sub < 2; sub++) {
                const int cb = kt * KTILE + sub * 64;
                const bool doCompute = cb <= (t0 + wm * 32 + 31);
                if (!doCompute) continue;

                float sacc[2][8][4] = {};
                #pragma unroll
                for (int ks = 0; ks < 4; ks++) {
                    uint32_t bh[4][4];
                    #pragma unroll
                    for (int jj = 0; jj < 4; jj++) {
                        int row = sub * 64 + jj * 16 + (lane & 7) + ((lane >> 4) << 3);
                        int c = ks * 2 + ((lane >> 3) & 1);
                        ldsm4(bh[jj], swz(ss, row, c));
                    }
                    #pragma unroll
                    for (int mt = 0; mt < 2; mt++)
                        #pragma unroll
                        for (int nt = 0; nt < 8; nt++)
                            mma16816(sacc[mt][nt], qf[mt][ks], &bh[nt >> 1][(nt & 1) * 2]);
                }

                #pragma unroll
                for (int mt = 0; mt < 2; mt++) {
                    const int rbase = t0 + wm * 32 + mt * 16;
                    // causal mask (diagonal subtiles only); logits already log2-scaled
                    if ((cb + 63) > rbase) {
                        #pragma unroll
                        for (int nt = 0; nt < 8; nt++)
                            #pragma unroll
                            for (int e = 0; e < 4; e++) {
                                int rg = rbase + (lane >> 2) + (e >> 1) * 8;
                                int cg = cb + nt * 8 + (lane & 3) * 2 + (e & 1);
                                if (cg > rg) sacc[mt][nt][e] = -1e30f;
                            }
                    }

                    #pragma unroll
                    for (int rh = 0; rh < 2; rh++) {
                        float mloc = -1e30f;
                        #pragma unroll
                        for (int nt = 0; nt < 8; nt++)
                            mloc = fmaxf(mloc, fmaxf(sacc[mt][nt][rh * 2], sacc[mt][nt][rh * 2 + 1]));
                        mloc = fmaxf(mloc, __shfl_xor_sync(0xffffffffu, mloc, 1));
                        mloc = fmaxf(mloc, __shfl_xor_sync(0xffffffffu, mloc, 2));
                        float mnew = fmaxf(m_prev[mt][rh], mloc);
                        float corr = exp2f(m_prev[mt][rh] - mnew);
                        m_prev[mt][rh] = mnew;
                        float ls = 0.0f;
                        #pragma unroll
                        for (int nt = 0; nt < 8; nt++) {
                            float d0 = sacc[mt][nt][rh * 2]     - mnew;
                            float d1 = sacc[mt][nt][rh * 2 + 1] - mnew;
                            uint32_t dh = f16x2_of(d0, d1);
                            uint32_t ph;
                            asm("ex2.approx.f16x2 %0, %1;" : "=r"(ph) : "r"(dh));
                            sacc[mt][nt][rh * 2] = __uint_as_float(ph);  // fragment, in place
                            float2 pf2 = __half22float2(*(__half2*)&ph);
                            ls += pf2.x + pf2.y;
                        }
                        ls += __shfl_xor_sync(0xffffffffu, ls, 1);
                        ls += __shfl_xor_sync(0xffffffffu, ls, 2);
                        l_run[mt][rh] = l_run[mt][rh] * corr + ls;
                        #pragma unroll
                        for (int nt = 0; nt < 8; nt++) {
                            oacc[mt][nt][rh * 2]     *= corr;
                            oacc[mt][nt][rh * 2 + 1] *= corr;
                        }
                    }
                }

                #pragma unroll
                for (int jp = 0; jp < 4; jp++) {
                    uint32_t vh[4][4];
                    #pragma unroll
                    for (int jd = 0; jd < 4; jd++) {
                        int row = sub * 64 + jp * 16 + (lane & 7) + (((lane >> 3) & 1) << 3);
                        int c = 2 * jd + (lane >> 4);
                        ldsm4t(vh[jd], swz(ss + 16384, row, c));
                    }
                    #pragma unroll
                    for (int mt = 0; mt < 2; mt++) {
                        uint32_t pa[4];
                        const float* f0 = sacc[mt][2 * jp];
                        const float* f1 = sacc[mt][2 * jp + 1];
                        pa[0] = __float_as_uint(f0[0]);   // rh0 pair (pre-packed fp16)
                        pa[1] = __float_as_uint(f0[2]);   // rh1 pair
                        pa[2] = __float_as_uint(f1[0]);
                        pa[3] = __float_as_uint(f1[2]);
                        #pragma unroll
                        for (int nt = 0; nt < 8; nt++)
                            mma16816(oacc[mt][nt], pa, &vh[nt >> 1][(nt & 1) * 2]);
                    }
                }
            }
            __syncthreads();
        }

        #pragma unroll
        for (int mt = 0; mt < 2; mt++)
            #pragma unroll
            for (int rh = 0; rh < 2; rh++) {
                float iv = 1.0f / l_run[mt][rh];
                #pragma unroll
                for (int nt = 0; nt < 8; nt++) {
                    float o0 = oacc[mt][nt][rh * 2] * iv;
                    float o1 = oacc[mt][nt][rh * 2 + 1] * iv;
                    size_t token = (size_t)(bT + t0 + wm * 32 + mt * 16 + (lane >> 2) + rh * 8);
                    of[(token * CC + h * HD + nt * 8 + (lane & 3) * 2) >> 1] = f16x2_of(o0, o1);
                }
            }
    }
}

// ---------------------------------------------------------------------------
// Launch
// ---------------------------------------------------------------------------
extern "C" void kernel_launch(void* const* d_in, const int* in_sizes, int n_in,
                              void* d_out, int out_size)
{
    const float* x      = (const float*)d_in[0];
    const float* qkv_w  = (const float*)d_in[1];
    const float* qkv_b  = (const float*)d_in[2];
    const float* out_w  = (const float*)d_in[3];
    const float* out_b  = (const float*)d_in[4];
    float* out = (float*)d_out;

    uint32_t *xf, *w1f, *w2f, *qf, *atf;
    int* ctr;
    cudaGetSymbolAddress((void**)&xf, g_xf);
    cudaGetSymbolAddress((void**)&w1f, g_w1f);
    cudaGetSymbolAddress((void**)&w2f, g_w2f);
    cudaGetSymbolAddress((void**)&qf, g_qkvf);
    cudaGetSymbolAddress((void**)&atf, g_atf);
    cudaGetSymbolAddress((void**)&ctr, g_ctr);

    cudaFuncSetAttribute(gemm_mma<true>,  cudaFuncAttributeMaxDynamicSharedMemorySize, GEMM_DSM);
    cudaFuncSetAttribute(gemm_mma<false>, cudaFuncAttributeMaxDynamicSharedMemorySize, GEMM_DSM);
    cudaFuncSetAttribute(attn_mma, cudaFuncAttributeMaxDynamicSharedMemorySize, ATTN_DSM);

    // reset dynamic-tile counters (async memset is graph-capturable)
    cudaMemsetAsync(ctr, 0, 4 * sizeof(int));

    // 0) fused fp32->fp16 converts
    {
        const int n0 = MTOK * CC / 4, n1 = C3 * CC / 4, n2 = CC * CC / 4;
        const int nt = n0 + n1 + n2;
        cvt_all<<<(nt + 255) / 256, 256>>>((const float4*)x, xf, n0,
                                           (const float4*)qkv_w, w1f, n1,
                                           (const float4*)out_w, w2f, n2);
    }
    // 1) QKV projection -> fp16 qkv; Q columns pre-scaled by 0.125*log2(e)
    gemm_mma<true><<<296, 256, GEMM_DSM>>>(xf, w1f, qkv_b, nullptr, qf,
                                           MTOK, C3, CC, C3 / 128,
                                           (MTOK / 128) * (C3 / 128), 1,
                                           CC, QSCALE);
    // 2) Causal flash attention -> fp16 (persistent, dynamic items)
    attn_mma<<<148, 256, ATTN_DSM>>>(qf, atf);
    // 3) Output projection -> fp32
    gemm_mma<false><<<296, 256, GEMM_DSM>>>(atf, w2f, out_b, out, nullptr,
                                            MTOK, CC, CC, CC / 128,
                                            (MTOK / 128) * (CC / 128), 3,
                                            0, 1.0f);
}

// round 17
// speedup vs baseline: 1.0763x; 1.0154x over previous
#include <cuda_runtime.h>
#include <cuda_fp16.h>
#include <cstdint>

// Problem constants
#define BB 4
#define TT 2048
#define CC 1024
#define HH 16
#define HD 64
#define MTOK (BB*TT)        // 8192
#define C3  (3*CC)          // 3072

// 0.125 (1/sqrt(64)) * log2(e): folded into Q so attention can use exp2
#define QSCALE 0.18033688f

// Scratch (allocation-guard-safe: __device__ globals). fp16 pairs stored as u32.
__device__ uint32_t g_xf[(size_t)MTOK * CC / 2];
__device__ uint32_t g_w1f[(size_t)C3 * CC / 2];
__device__ uint32_t g_w2f[(size_t)CC * CC / 2];
__device__ uint32_t g_qkvf[(size_t)MTOK * C3 / 2];
__device__ uint32_t g_atf[(size_t)MTOK * CC / 2];
__device__ int g_ctr[4];   // dynamic tile counters (reset each launch)

// ---------------------------------------------------------------------------
// Helpers
// ---------------------------------------------------------------------------
__device__ __forceinline__ uint32_t smem_u32(const void* p) {
    uint32_t a;
    asm("{ .reg .u64 t; cvta.to.shared.u64 t, %1; cvt.u32.u64 %0, t; }" : "=r"(a) : "l"(p));
    return a;
}
__device__ __forceinline__ uint32_t f16x2_of(float lo, float hi) {
    uint32_t r;
    asm("cvt.rn.f16x2.f32 %0, %1, %2;" : "=r"(r) : "f"(hi), "f"(lo));
    return r;
}
__device__ __forceinline__ void cp16(uint32_t s, const void* g) {
    asm volatile("cp.async.cg.shared.global [%0], [%1], 16;" :: "r"(s), "l"(g) : "memory");
}
__device__ __forceinline__ void cpcommit() {
    asm volatile("cp.async.commit_group;" ::: "memory");
}
__device__ __forceinline__ void cpwait0() { asm volatile("cp.async.wait_group 0;" ::: "memory"); }
__device__ __forceinline__ void cpwait1() { asm volatile("cp.async.wait_group 1;" ::: "memory"); }
__device__ __forceinline__ void ldsm4(uint32_t* r, uint32_t a) {
    asm volatile("ldmatrix.sync.aligned.m8n8.x4.shared.b16 {%0,%1,%2,%3}, [%4];"
        : "=r"(r[0]), "=r"(r[1]), "=r"(r[2]), "=r"(r[3]) : "r"(a));
}
__device__ __forceinline__ void ldsm4t(uint32_t* r, uint32_t a) {
    asm volatile("ldmatrix.sync.aligned.m8n8.x4.trans.shared.b16 {%0,%1,%2,%3}, [%4];"
        : "=r"(r[0]), "=r"(r[1]), "=r"(r[2]), "=r"(r[3]) : "r"(a));
}
__device__ __forceinline__ void mma16816(float* c, const uint32_t* a, const uint32_t* b) {
    asm volatile("mma.sync.aligned.m16n8k16.row.col.f32.f16.f16.f32 "
        "{%0,%1,%2,%3}, {%4,%5,%6,%7}, {%8,%9}, {%0,%1,%2,%3};"
        : "+f"(c[0]), "+f"(c[1]), "+f"(c[2]), "+f"(c[3])
        : "r"(a[0]), "r"(a[1]), "r"(a[2]), "r"(a[3]), "r"(b[0]), "r"(b[1]));
}
// 128B-row swizzle: 8 chunks of 16B, chunk ^ (row & 7)
__device__ __forceinline__ uint32_t swz(uint32_t base, int row, int chunk) {
    return base + (uint32_t)(row * 128) + (uint32_t)((chunk ^ (row & 7)) << 4);
}

// ---------------------------------------------------------------------------
// Fused conversion: fp32 -> fp16 for x, w1, w2 in one launch
// ---------------------------------------------------------------------------
__global__ void cvt_all(const float4* __restrict__ s0, uint32_t* __restrict__ d0, int n0,
                        const float4* __restrict__ s1, uint32_t* __restrict__ d1, int n1,
                        const float4* __restrict__ s2, uint32_t* __restrict__ d2, int n2)
{
    int i = blockIdx.x * blockDim.x + threadIdx.x;
    const float4* s; uint32_t* d; int j;
    if (i < n0)            { s = s0; d = d0; j = i; }
    else if (i < n0 + n1)  { s = s1; d = d1; j = i - n0; }
    else if (i < n0+n1+n2) { s = s2; d = d2; j = i - n0 - n1; }
    else return;
    float4 f = s[j];
    *(uint2*)&d[2 * j] = make_uint2(f16x2_of(f.x, f.y), f16x2_of(f.z, f.w));
}

// ---------------------------------------------------------------------------
// Persistent GEMM via mma.sync (single-pass fp16), BK=64, warp tile 64x32.
// Grid 296 CTAs; tiles claimed dynamically via g_ctr[ctr_idx].
// qcols/qmul: columns < qcols get (acc+bias)*qmul (Q pre-scaling for attn).
// ---------------------------------------------------------------------------
#define BK 64
#define STAGES 3
#define SBYTES 32768
#define GEMM_DSM (STAGES * SBYTES + 1024)

template<bool OUT_HALF>
__global__ void __launch_bounds__(256, 2)
gemm_mma(const uint32_t* __restrict__ A2, const uint32_t* __restrict__ B2,
         const float* __restrict__ bias,
         float* __restrict__ OutF, uint32_t* __restrict__ OutH,
         int M, int N, int K, int ntN, int ntiles, int ctr_idx,
         int qcols, float qmul)
{
    extern __shared__ char dsm[];
    __shared__ int s_tile;
    const uint32_t sbase = (smem_u32(dsm) + 1023u) & ~1023u;

    const int tid  = threadIdx.x;
    const int lane = tid & 31;
    const int warp = tid >> 5;
    const int wm = warp & 1;
    const int wn = warp >> 1;
    const int lr = tid >> 3;
    const int lc = tid & 7;
    const int NKI = K / BK;

    for (;;) {
        if (tid == 0) s_tile = atomicAdd(&g_ctr[ctr_idx], 1);
        __syncthreads();
        const int t = s_tile;
        if (t >= ntiles) break;
        const int m0 = (t / ntN) * 128;
        const int n0 = (t % ntN) * 128;

        const char* pA = (const char*)A2 + (size_t)m0 * K * 2;
        const char* pB = (const char*)B2 + (size_t)n0 * K * 2;

        float acc[4][4][4] = {};

        auto load_stage = [&](int s, int it) {
            const uint32_t ss = sbase + s * SBYTES;
            const int gko = it * BK * 2;
            #pragma unroll
            for (int i = 0; i < 4; i++) {
                int r = lr + i * 32;
                cp16(swz(ss, r, lc), pA + (size_t)r * K * 2 + gko + lc * 16);
                cp16(swz(ss + 16384, r, lc), pB + (size_t)r * K * 2 + gko + lc * 16);
            }
        };
        auto compute_stage = [&](int s) {
            const uint32_t ss = sbase + s * SBYTES;
            #pragma unroll
            for (int ks = 0; ks < 4; ks++) {
                uint32_t a[4][4];
                #pragma unroll
                for (int mt = 0; mt < 4; mt++) {
                    int row = wm * 64 + mt * 16 + (lane & 15);
                    int kc  = ks * 2 + (lane >> 4);
                    ldsm4(a[mt], swz(ss, row, kc));
                }
                uint32_t b[2][4];
                #pragma unroll
                for (int jj = 0; jj < 2; jj++) {
                    int row = wn * 32 + jj * 16 + (lane & 7) + ((lane >> 4) << 3);
                    int kc  = ks * 2 + ((lane >> 3) & 1);
                    ldsm4(b[jj], swz(ss + 16384, row, kc));
                }
                #pragma unroll
                for (int mt = 0; mt < 4; mt++)
                    #pragma unroll
                    for (int nt = 0; nt < 4; nt++)
                        mma16816(acc[mt][nt], a[mt], &b[nt >> 1][(nt & 1) * 2]);
            }
        };

        #pragma unroll
        for (int s = 0; s < STAGES - 1; s++) { load_stage(s, s); cpcommit(); }

        for (int it = 0; it < NKI; it++) {
            asm volatile("cp.async.wait_group %0;" :: "n"(STAGES - 2) : "memory");
            __syncthreads();
            const int nit = it + STAGES - 1;
            if (nit < NKI) load_stage(nit % STAGES, nit);
            cpcommit();
            compute_stage(it % STAGES);
        }

        const int rr = lane >> 2;
        const int cc = (lane & 3) * 2;
        #pragma unroll
        for (int mt = 0; mt < 4; mt++)
            #pragma unroll
            for (int nt = 0; nt < 4; nt++) {
                const int col = n0 + wn * 32 + nt * 8 + cc;
                const float b0 = bias[col], b1 = bias[col + 1];
                const float mul = (col < qcols) ? qmul : 1.0f;
                #pragma unroll
                for (int hf = 0; hf < 2; hf++) {
                    const int row = m0 + wm * 64 + mt * 16 + rr + hf * 8;
                    float v0 = (acc[mt][nt][hf * 2 + 0] + b0) * mul;
                    float v1 = (acc[mt][nt][hf * 2 + 1] + b1) * mul;
                    if (OUT_HALF) {
                        OutH[((size_t)row * N + col) >> 1] = f16x2_of(v0, v1);
                    } else {
                        *(float2*)&OutF[(size_t)row * N + col] = make_float2(v0, v1);
                    }
                }
            }
    }
}

// ---------------------------------------------------------------------------
// Persistent flash attention (causal), fp16, QTILE=256, KTILE=128.
// Q pre-scaled by 0.125*log2e in gemm1. Softmax exp via ex2.approx.f16x2,
// l accumulated in packed fp16 (add.rn.f16x2), one unpack per row-half.
// ---------------------------------------------------------------------------
#define QTILE 256
#define KTILE 128
#define ASTAGE 32768
#define ATTN_DSM (32768 + 2 * ASTAGE + 1024)
#define NQT (TT / QTILE)          // 8
#define NITEMS (NQT * HH * BB)    // 512

__global__ void __launch_bounds__(256, 1)
attn_mma(const uint32_t* __restrict__ qkvf, uint32_t* __restrict__ of)
{
    extern __shared__ char dsm[];
    __shared__ int s_item;
    const uint32_t sb = (smem_u32(dsm) + 1023u) & ~1023u;
    const uint32_t sQ = sb, sStage = sb + 32768;

    const int tid = threadIdx.x;
    const int lane = tid & 31;
    const int wm = tid >> 5;
    const char* pf = (const char*)qkvf;

    for (;;) {
        if (tid == 0) s_item = atomicAdd(&g_ctr[2], 1);
        __syncthreads();
        const int w = s_item;
        if (w >= NITEMS) break;
        const int qt = NQT - 1 - (w / (HH * BB));       // heavy first
        const int hb = w % (HH * BB);
        const int h  = hb >> 2;
        const int b  = hb & 3;
        const int t0 = qt * QTILE;
        const int bT = b * TT;
        const int nkt = 2 * (qt + 1);

        auto load_q = [&]() {
            #pragma unroll
            for (int i = 0; i < 8; i++) {
                int idx = i * 256 + tid;
                int r = idx >> 3, c = idx & 7;
                cp16(swz(sQ, r, c), pf + ((size_t)(bT + t0 + r) * C3 + h * HD) * 2 + c * 16);
            }
        };
        auto load_kv = [&](int kt, int buf) {
            const uint32_t ss = sStage + buf * ASTAGE;
            const int c = tid & 7;
            #pragma unroll
            for (int i = 0; i < 4; i++) {
                int r = (tid >> 3) + i * 32;
                size_t rowg = (size_t)(bT + kt * KTILE + r) * C3;
                cp16(swz(ss,         r, c), pf + (rowg + CC + h * HD) * 2 + c * 16);
                cp16(swz(ss + 16384, r, c), pf + (rowg + 2 * CC + h * HD) * 2 + c * 16);
            }
        };

        load_q();
        load_kv(0, 0);
        cpcommit();

        uint32_t qf[2][4][4];
        float oacc[2][8][4] = {};
        float m_prev[2][2] = {{-1e30f, -1e30f}, {-1e30f, -1e30f}};
        float l_run[2][2] = {};
        bool qload = false;

        for (int kt = 0; kt < nkt; kt++) {
            if (kt + 1 < nkt) { load_kv(kt + 1, (kt + 1) & 1); cpcommit(); cpwait1(); }
            else cpwait0();
            __syncthreads();

            if (!qload) {
                qload = true;
                #pragma unroll
                for (int mt = 0; mt < 2; mt++)
                    #pragma unroll
                    for (int ks = 0; ks < 4; ks++) {
                        int row = wm * 32 + mt * 16 + (lane & 15);
                        int c = ks * 2 + (lane >> 4);
                        ldsm4(qf[mt][ks], swz(sQ, row, c));
                    }
            }

            const uint32_t ss = sStage + (kt & 1) * ASTAGE;

            #pragma unroll
            for (int sub = 0; sub < 2; sub++) {
                const int cb = kt * KTILE + sub * 64;
                const bool doCompute = cb <= (t0 + wm * 32 + 31);
                if (!doCompute) continue;

                float sacc[2][8][4] = {};
                #pragma unroll
                for (int ks = 0; ks < 4; ks++) {
                    uint32_t bh[4][4];
                    #pragma unroll
                    for (int jj = 0; jj < 4; jj++) {
                        int row = sub * 64 + jj * 16 + (lane & 7) + ((lane >> 4) << 3);
                        int c = ks * 2 + ((lane >> 3) & 1);
                        ldsm4(bh[jj], swz(ss, row, c));
                    }
                    #pragma unroll
                    for (int mt = 0; mt < 2; mt++)
                        #pragma unroll
                        for (int nt = 0; nt < 8; nt++)
                            mma16816(sacc[mt][nt], qf[mt][ks], &bh[nt >> 1][(nt & 1) * 2]);
                }

                #pragma unroll
                for (int mt = 0; mt < 2; mt++) {
                    const int rbase = t0 + wm * 32 + mt * 16;
                    // causal mask (diagonal subtiles only); logits already log2-scaled
                    if ((cb + 63) > rbase) {
                        #pragma unroll
                        for (int nt = 0; nt < 8; nt++)
                            #pragma unroll
                            for (int e = 0; e < 4; e++) {
                                int rg = rbase + (lane >> 2) + (e >> 1) * 8;
                                int cg = cb + nt * 8 + (lane & 3) * 2 + (e & 1);
                                if (cg > rg) sacc[mt][nt][e] = -1e30f;
                            }
                    }

                    #pragma unroll
                    for (int rh = 0; rh < 2; rh++) {
                        float mloc = -1e30f;
                        #pragma unroll
                        for (int nt = 0; nt < 8; nt++)
                            mloc = fmaxf(mloc, fmaxf(sacc[mt][nt][rh * 2], sacc[mt][nt][rh * 2 + 1]));
                        mloc = fmaxf(mloc, __shfl_xor_sync(0xffffffffu, mloc, 1));
                        mloc = fmaxf(mloc, __shfl_xor_sync(0xffffffffu, mloc, 2));
                        float mnew = fmaxf(m_prev[mt][rh], mloc);
                        float corr = exp2f(m_prev[mt][rh] - mnew);
                        m_prev[mt][rh] = mnew;
                        uint32_t lacc = 0;                       // packed fp16 pair-sum
                        #pragma unroll
                        for (int nt = 0; nt < 8; nt++) {
                            float d0 = sacc[mt][nt][rh * 2]     - mnew;
                            float d1 = sacc[mt][nt][rh * 2 + 1] - mnew;
                            uint32_t dh = f16x2_of(d0, d1);
                            uint32_t ph;
                            asm("ex2.approx.f16x2 %0, %1;" : "=r"(ph) : "r"(dh));
                            sacc[mt][nt][rh * 2] = __uint_as_float(ph);  // fragment, in place
                            asm("add.rn.f16x2 %0, %1, %2;" : "=r"(lacc) : "r"(lacc), "r"(ph));
                        }
                        float2 lf2 = __half22float2(*(__half2*)&lacc);
                        float ls = lf2.x + lf2.y;
                        ls += __shfl_xor_sync(0xffffffffu, ls, 1);
                        ls += __shfl_xor_sync(0xffffffffu, ls, 2);
                        l_run[mt][rh] = l_run[mt][rh] * corr + ls;
                        #pragma unroll
                        for (int nt = 0; nt < 8; nt++) {
                            oacc[mt][nt][rh * 2]     *= corr;
                            oacc[mt][nt][rh * 2 + 1] *= corr;
                        }
                    }
                }

                #pragma unroll
                for (int jp = 0; jp < 4; jp++) {
                    uint32_t vh[4][4];
                    #pragma unroll
                    for (int jd = 0; jd < 4; jd++) {
                        int row = sub * 64 + jp * 16 + (lane & 7) + (((lane >> 3) & 1) << 3);
                        int c = 2 * jd + (lane >> 4);
                        ldsm4t(vh[jd], swz(ss + 16384, row, c));
                    }
                    #pragma unroll
                    for (int mt = 0; mt < 2; mt++) {
                        uint32_t pa[4];
                        const float* f0 = sacc[mt][2 * jp];
                        const float* f1 = sacc[mt][2 * jp + 1];
                        pa[0] = __float_as_uint(f0[0]);   // rh0 pair (pre-packed fp16)
                        pa[1] = __float_as_uint(f0[2]);   // rh1 pair
                        pa[2] = __float_as_uint(f1[0]);
                        pa[3] = __float_as_uint(f1[2]);
                        #pragma unroll
                        for (int nt = 0; nt < 8; nt++)
                            mma16816(oacc[mt][nt], pa, &vh[nt >> 1][(nt & 1) * 2]);
                    }
                }
            }
            __syncthreads();
        }

        #pragma unroll
        for (int mt = 0; mt < 2; mt++)
            #pragma unroll
            for (int rh = 0; rh < 2; rh++) {
                float iv = 1.0f / l_run[mt][rh];
                #pragma unroll
                for (int nt = 0; nt < 8; nt++) {
                    float o0 = oacc[mt][nt][rh * 2] * iv;
                    float o1 = oacc[mt][nt][rh * 2 + 1] * iv;
                    size_t token = (size_t)(bT + t0 + wm * 32 + mt * 16 + (lane >> 2) + rh * 8);
                    of[(token * CC + h * HD + nt * 8 + (lane & 3) * 2) >> 1] = f16x2_of(o0, o1);
                }
            }
    }
}

// ---------------------------------------------------------------------------
// Launch
// ---------------------------------------------------------------------------
extern "C" void kernel_launch(void* const* d_in, const int* in_sizes, int n_in,
                              void* d_out, int out_size)
{
    const float* x      = (const float*)d_in[0];
    const float* qkv_w  = (const float*)d_in[1];
    const float* qkv_b  = (const float*)d_in[2];
    const float* out_w  = (const float*)d_in[3];
    const float* out_b  = (const float*)d_in[4];
    float* out = (float*)d_out;

    uint32_t *xf, *w1f, *w2f, *qf, *atf;
    int* ctr;
    cudaGetSymbolAddress((void**)&xf, g_xf);
    cudaGetSymbolAddress((void**)&w1f, g_w1f);
    cudaGetSymbolAddress((void**)&w2f, g_w2f);
    cudaGetSymbolAddress((void**)&qf, g_qkvf);
    cudaGetSymbolAddress((void**)&atf, g_atf);
    cudaGetSymbolAddress((void**)&ctr, g_ctr);

    cudaFuncSetAttribute(gemm_mma<true>,  cudaFuncAttributeMaxDynamicSharedMemorySize, GEMM_DSM);
    cudaFuncSetAttribute(gemm_mma<false>, cudaFuncAttributeMaxDynamicSharedMemorySize, GEMM_DSM);
    cudaFuncSetAttribute(attn_mma, cudaFuncAttributeMaxDynamicSharedMemorySize, ATTN_DSM);

    // reset dynamic-tile counters (async memset is graph-capturable)
    cudaMemsetAsync(ctr, 0, 4 * sizeof(int));

    // 0) fused fp32->fp16 converts
    {
        const int n0 = MTOK * CC / 4, n1 = C3 * CC / 4, n2 = CC * CC / 4;
        const int nt = n0 + n1 + n2;
        cvt_all<<<(nt + 255) / 256, 256>>>((const float4*)x, xf, n0,
                                           (const float4*)qkv_w, w1f, n1,
                                           (const float4*)out_w, w2f, n2);
    }
    // 1) QKV projection -> fp16 qkv; Q columns pre-scaled by 0.125*log2(e)
    gemm_mma<true><<<296, 256, GEMM_DSM>>>(xf, w1f, qkv_b, nullptr, qf,
                                           MTOK, C3, CC, C3 / 128,
                                           (MTOK / 128) * (C3 / 128), 1,
                                           CC, QSCALE);
    // 2) Causal flash attention -> fp16 (persistent, dynamic items)
    attn_mma<<<148, 256, ATTN_DSM>>>(qf, atf);
    // 3) Output projection -> fp32
    gemm_mma<false><<<296, 256, GEMM_DSM>>>(atf, w2f, out_b, out, nullptr,
                                            MTOK, CC, CC, CC / 128,
                                            (MTOK / 128) * (CC / 128), 3,
                                            0, 1.0f);
}